// round 15
// baseline (speedup 1.0000x reference)
#include <cuda_runtime.h>
#include <cuda_bf16.h>
#include <cstdint>
#include <math.h>

// Problem constants
#define NB   16
#define LL   512
#define DD   256
#define FF   256
#define TT   4096
#define MM   (NB * LL)        // 8192 rows
#define KTOT 768              // D * 3
#define EPS  1e-5f

// ---------------- scratch (static device globals; no allocs) ----------------
__device__ __align__(16) float g_h1[MM * FF];
__device__ __align__(16) __nv_bfloat16 g_b1hi[FF * KTOT];
__device__ __align__(16) __nv_bfloat16 g_b1lo[FF * KTOT];
__device__ __align__(16) __nv_bfloat16 g_b2hi[FF * KTOT];
__device__ __align__(16) __nv_bfloat16 g_b2lo[FF * KTOT];
__device__ int   g_idx[NB * TT];    // length-regulation gather index (-1 = pad)

// ==== fused weight prep (blocks 0..767) + cumsum->index scatter (block 768) ==
__global__ void prep_b_cumsum_kernel(const float* __restrict__ w1,
                                     const float* __restrict__ w2,
                                     const int* __restrict__ target) {
    if (blockIdx.x == 768) {
        // 256 threads = 8 warps; warp w handles sequences 2w, 2w+1
        int wid = threadIdx.x >> 5, lane = threadIdx.x & 31;
#pragma unroll
        for (int r = 0; r < 2; ++r) {
            int n = wid * 2 + r;
            const int* src = target + n * LL + lane * 16;
            int v[16];
#pragma unroll
            for (int j = 0; j < 4; ++j)
                *(int4*)(v + j * 4) = *(const int4*)(src + j * 4);
#pragma unroll
            for (int j = 1; j < 16; ++j) v[j] += v[j - 1];
            int total = v[15];
            int pre = total;
#pragma unroll
            for (int o = 1; o < 32; o <<= 1) {
                int t = __shfl_up_sync(0xffffffffu, pre, o);
                if (lane >= o) pre += t;
            }
            pre -= total;   // exclusive prefix before this lane's chunk
#pragma unroll
            for (int j = 0; j < 16; ++j) v[j] += pre;   // global inclusive
            // scatter: element l=lane*16+j covers t in [start, v[j])
            int* idxn = g_idx + n * TT;
            int start = pre;
#pragma unroll
            for (int j = 0; j < 16; ++j) {
                int l = lane * 16 + j;
                for (int t = start; t < v[j]; ++t) idxn[t] = l;
                start = v[j];
            }
            int tot = __shfl_sync(0xffffffffu, v[15], 31);
            for (int t = tot + lane; t < TT; t += 32) idxn[t] = -1;
        }
        return;
    }
    int i = blockIdx.x * 256 + threadIdx.x;     // over 256*768
    int f = i / KTOT;
    int kf = i - f * KTOT;
    int k = kf >> 8;
    int d = kf & 255;
    float v1 = w1[f * KTOT + d * 3 + k];
    float v2 = w2[f * KTOT + d * 3 + k];
    __nv_bfloat16 h1 = __float2bfloat16_rn(v1);
    __nv_bfloat16 h2 = __float2bfloat16_rn(v2);
    g_b1hi[i] = h1;
    g_b1lo[i] = __float2bfloat16_rn(v1 - __bfloat162float(h1));
    g_b2hi[i] = h2;
    g_b2lo[i] = __float2bfloat16_rn(v2 - __bfloat162float(h2));
}

// ============== fused conv(K=3) GEMM + LayerNorm + ReLU (+ linear) ==========
// Per CTA: 64 rows x 256 cols. 512 threads = 16 warps (2m x 8n), warp tile 32x32.
// K loop: 24 chunks of 32 (3 taps x 8 d-chunks), bf16 hi/lo 3-pass HMMA.
// (R6-proven scalar-LDS fragment path; ldmatrix variant measured slower.)

#define ST_BYTES   51200            // one stage: Ahi|Alo|Bhi|Blo (80B rows)
#define OFF_AHI    0                // 64 rows x 80B
#define OFF_ALO    5120
#define OFF_BHI    10240            // 256 rows x 80B
#define OFF_BLO    30720
#define OFF_PART_S (2 * ST_BYTES)           // 8 x 64 floats
#define OFF_PART_Q (OFF_PART_S + 2048)
#define OFF_MEAN   (OFF_PART_Q + 2048)      // 64 floats
#define OFF_RSTD   (OFF_MEAN + 256)
#define SMEM_CONV  (OFF_RSTD + 256)

__device__ __forceinline__ void hmma(float* d, const uint32_t* a, const uint32_t* b) {
    asm volatile(
        "mma.sync.aligned.m16n8k16.row.col.f32.bf16.bf16.f32 "
        "{%0,%1,%2,%3}, {%4,%5,%6,%7}, {%8,%9}, {%0,%1,%2,%3};"
        : "+f"(d[0]), "+f"(d[1]), "+f"(d[2]), "+f"(d[3])
        : "r"(a[0]), "r"(a[1]), "r"(a[2]), "r"(a[3]), "r"(b[0]), "r"(b[1]));
}

__device__ __forceinline__ uint32_t pack2(float a, float b) {
    __nv_bfloat162 t = __floats2bfloat162_rn(a, b);
    return *reinterpret_cast<uint32_t*>(&t);
}

template <bool DO_LIN>
__global__ __launch_bounds__(512, 1)
void conv_fused_kernel(const float* __restrict__ A,
                       const __nv_bfloat16* __restrict__ Bhi,
                       const __nv_bfloat16* __restrict__ Blo,
                       const float* __restrict__ bias,
                       const float* __restrict__ gam,
                       const float* __restrict__ bet,
                       const float* __restrict__ lw,
                       const float* __restrict__ lb,
                       float* __restrict__ out)   // h1 if !DO_LIN, dpo if DO_LIN
{
    extern __shared__ char smem[];
    const int tid = threadIdx.x;
    const int wid = tid >> 5;
    const int lane = tid & 31;
    const int g = lane >> 2;          // groupID
    const int t4 = lane & 3;          // thread-in-group
    const int wm = wid >> 3;          // 0..1
    const int wn = wid & 7;           // 0..7
    const int bm = blockIdx.x * 64;
    const int n = bm >> 9;
    const int l0 = bm & 511;

    float4 aval;
    uint4  bhv[2], blv[2];
    const int arow = tid >> 3;        // A: row 0..63
    const int akq = tid & 7;          // float4 along d
    const int brow0 = tid >> 2, bkq0 = tid & 3;
    const int brow1 = (tid + 512) >> 2, bkq1 = tid & 3;

    auto prefetch = [&](int c) {
        const int tap = c >> 3;
        const int dc = (c & 7) * 32;
        int lsrc = l0 + arow + tap - 1;
        aval = make_float4(0.f, 0.f, 0.f, 0.f);
        if (lsrc >= 0 && lsrc < LL)
            aval = *(const float4*)(A + (size_t)((n << 9) + lsrc) * DD + dc + akq * 4);
        const int kfb = tap * 256 + dc;
        bhv[0] = *(const uint4*)(Bhi + (size_t)brow0 * KTOT + kfb + bkq0 * 8);
        bhv[1] = *(const uint4*)(Bhi + (size_t)brow1 * KTOT + kfb + bkq1 * 8);
        blv[0] = *(const uint4*)(Blo + (size_t)brow0 * KTOT + kfb + bkq0 * 8);
        blv[1] = *(const uint4*)(Blo + (size_t)brow1 * KTOT + kfb + bkq1 * 8);
    };

    auto store_stage = [&](int s) {
        char* stg = smem + s * ST_BYTES;
        __nv_bfloat16 hx = __float2bfloat16_rn(aval.x);
        __nv_bfloat16 hy = __float2bfloat16_rn(aval.y);
        __nv_bfloat16 hz = __float2bfloat16_rn(aval.z);
        __nv_bfloat16 hw = __float2bfloat16_rn(aval.w);
        uint32_t hi01, hi23;
        { __nv_bfloat162 p; p.x = hx; p.y = hy; hi01 = *reinterpret_cast<uint32_t*>(&p); }
        { __nv_bfloat162 p; p.x = hz; p.y = hw; hi23 = *reinterpret_cast<uint32_t*>(&p); }
        uint32_t lo01 = pack2(aval.x - __bfloat162float(hx), aval.y - __bfloat162float(hy));
        uint32_t lo23 = pack2(aval.z - __bfloat162float(hz), aval.w - __bfloat162float(hw));
        *(uint2*)(stg + OFF_AHI + arow * 80 + akq * 8) = make_uint2(hi01, hi23);
        *(uint2*)(stg + OFF_ALO + arow * 80 + akq * 8) = make_uint2(lo01, lo23);
        *(uint4*)(stg + OFF_BHI + brow0 * 80 + bkq0 * 16) = bhv[0];
        *(uint4*)(stg + OFF_BHI + brow1 * 80 + bkq1 * 16) = bhv[1];
        *(uint4*)(stg + OFF_BLO + brow0 * 80 + bkq0 * 16) = blv[0];
        *(uint4*)(stg + OFF_BLO + brow1 * 80 + bkq1 * 16) = blv[1];
    };

    float acc[2][4][4];
#pragma unroll
    for (int i = 0; i < 2; i++)
#pragma unroll
        for (int j = 0; j < 4; j++)
#pragma unroll
            for (int c = 0; c < 4; c++) acc[i][j][c] = 0.f;

    // prologue: stage 0 stored, regs hold chunk 1
    prefetch(0);
    store_stage(0);
    prefetch(1);

#pragma unroll 1
    for (int c = 0; c < 24; ++c) {
        __syncthreads();   // buf c&1 published; buf (c+1)&1 free for overwrite
        if (c < 23) store_stage((c + 1) & 1);   // from regs prefetched at c-1
        if (c < 22) prefetch(c + 2);            // LDGs overlap compute(c)
        const char* stg = smem + (c & 1) * ST_BYTES;
#pragma unroll
        for (int ks = 0; ks < 2; ++ks) {
            uint32_t ah[2][4], al[2][4], bh[4][2], bl[4][2];
#pragma unroll
            for (int ms = 0; ms < 2; ++ms) {
                const char* base = stg + OFF_AHI + (wm * 32 + ms * 16 + g) * 80 + ks * 32 + t4 * 4;
                ah[ms][0] = *(const uint32_t*)(base);
                ah[ms][1] = *(const uint32_t*)(base + 8 * 80);
                ah[ms][2] = *(const uint32_t*)(base + 16);
                ah[ms][3] = *(const uint32_t*)(base + 8 * 80 + 16);
            }
#pragma unroll
            for (int ns = 0; ns < 4; ++ns) {
                const char* base = stg + OFF_BHI + (wn * 32 + ns * 8 + g) * 80 + ks * 32 + t4 * 4;
                bh[ns][0] = *(const uint32_t*)(base);
                bh[ns][1] = *(const uint32_t*)(base + 16);
            }
#pragma unroll
            for (int ms = 0; ms < 2; ++ms)
#pragma unroll
                for (int ns = 0; ns < 4; ++ns) hmma(acc[ms][ns], ah[ms], bh[ns]);
#pragma unroll
            for (int ns = 0; ns < 4; ++ns) {
                const char* base = stg + OFF_BLO + (wn * 32 + ns * 8 + g) * 80 + ks * 32 + t4 * 4;
                bl[ns][0] = *(const uint32_t*)(base);
                bl[ns][1] = *(const uint32_t*)(base + 16);
            }
#pragma unroll
            for (int ms = 0; ms < 2; ++ms)
#pragma unroll
                for (int ns = 0; ns < 4; ++ns) hmma(acc[ms][ns], ah[ms], bl[ns]);
#pragma unroll
            for (int ms = 0; ms < 2; ++ms) {
                const char* base = stg + OFF_ALO + (wm * 32 + ms * 16 + g) * 80 + ks * 32 + t4 * 4;
                al[ms][0] = *(const uint32_t*)(base);
                al[ms][1] = *(const uint32_t*)(base + 8 * 80);
                al[ms][2] = *(const uint32_t*)(base + 16);
                al[ms][3] = *(const uint32_t*)(base + 8 * 80 + 16);
            }
#pragma unroll
            for (int ms = 0; ms < 2; ++ms)
#pragma unroll
                for (int ns = 0; ns < 4; ++ns) hmma(acc[ms][ns], al[ms], bh[ns]);
        }
    }

    // ---------------- epilogue: bias + LayerNorm + ReLU (+ linear) ----------------
    float* partS = (float*)(smem + OFF_PART_S);   // [8][64]
    float* partQ = (float*)(smem + OFF_PART_Q);   // [8][64]
    float* meanA = (float*)(smem + OFF_MEAN);     // [64]
    float* rstdA = (float*)(smem + OFF_RSTD);     // [64]

    float2 bs[4], gm[4], bt[4], lwv[4];
#pragma unroll
    for (int ns = 0; ns < 4; ++ns) {
        int col = wn * 32 + ns * 8 + t4 * 2;
        bs[ns] = *(const float2*)(bias + col);
        gm[ns] = *(const float2*)(gam + col);
        bt[ns] = *(const float2*)(bet + col);
        if (DO_LIN) lwv[ns] = *(const float2*)(lw + col);
    }
#pragma unroll
    for (int ms = 0; ms < 2; ++ms)
#pragma unroll
        for (int ns = 0; ns < 4; ++ns) {
            acc[ms][ns][0] += bs[ns].x; acc[ms][ns][1] += bs[ns].y;
            acc[ms][ns][2] += bs[ns].x; acc[ms][ns][3] += bs[ns].y;
        }
    __syncthreads();   // mainloop smem reads done before stats-area writes
#pragma unroll
    for (int ms = 0; ms < 2; ++ms) {
        float s0 = 0.f, q0 = 0.f, s1 = 0.f, q1 = 0.f;
#pragma unroll
        for (int ns = 0; ns < 4; ++ns) {
            s0 += acc[ms][ns][0] + acc[ms][ns][1];
            q0 += acc[ms][ns][0] * acc[ms][ns][0] + acc[ms][ns][1] * acc[ms][ns][1];
            s1 += acc[ms][ns][2] + acc[ms][ns][3];
            q1 += acc[ms][ns][2] * acc[ms][ns][2] + acc[ms][ns][3] * acc[ms][ns][3];
        }
#pragma unroll
        for (int o = 1; o <= 2; o <<= 1) {
            s0 += __shfl_xor_sync(0xffffffffu, s0, o);
            q0 += __shfl_xor_sync(0xffffffffu, q0, o);
            s1 += __shfl_xor_sync(0xffffffffu, s1, o);
            q1 += __shfl_xor_sync(0xffffffffu, q1, o);
        }
        if (t4 == 0) {
            int r0 = wm * 32 + ms * 16 + g;
            partS[wn * 64 + r0] = s0;      partQ[wn * 64 + r0] = q0;
            partS[wn * 64 + r0 + 8] = s1;  partQ[wn * 64 + r0 + 8] = q1;
        }
    }
    __syncthreads();
    if (tid < 64) {
        float s = 0.f, q = 0.f;
#pragma unroll
        for (int w = 0; w < 8; ++w) { s += partS[w * 64 + tid]; q += partQ[w * 64 + tid]; }
        float mean = s * (1.f / 256.f);
        float var = q * (1.f / 256.f) - mean * mean;
        meanA[tid] = mean;
        rstdA[tid] = rsqrtf(var + EPS);
    }
    __syncthreads();

    float mu[2][2], rs[2][2];
#pragma unroll
    for (int ms = 0; ms < 2; ++ms)
#pragma unroll
        for (int h = 0; h < 2; ++h) {
            int lr = wm * 32 + ms * 16 + h * 8 + g;
            mu[ms][h] = meanA[lr];
            rs[ms][h] = rstdA[lr];
        }
    float y[2][4][4];
#pragma unroll
    for (int ms = 0; ms < 2; ++ms)
#pragma unroll
        for (int ns = 0; ns < 4; ++ns) {
            y[ms][ns][0] = fmaxf((acc[ms][ns][0] - mu[ms][0]) * rs[ms][0] * gm[ns].x + bt[ns].x, 0.f);
            y[ms][ns][1] = fmaxf((acc[ms][ns][1] - mu[ms][0]) * rs[ms][0] * gm[ns].y + bt[ns].y, 0.f);
            y[ms][ns][2] = fmaxf((acc[ms][ns][2] - mu[ms][1]) * rs[ms][1] * gm[ns].x + bt[ns].x, 0.f);
            y[ms][ns][3] = fmaxf((acc[ms][ns][3] - mu[ms][1]) * rs[ms][1] * gm[ns].y + bt[ns].y, 0.f);
        }

    if (!DO_LIN) {
#pragma unroll
        for (int ms = 0; ms < 2; ++ms)
#pragma unroll
            for (int h = 0; h < 2; ++h) {
                int grow = bm + wm * 32 + ms * 16 + h * 8 + g;
#pragma unroll
                for (int ns = 0; ns < 4; ++ns) {
                    int col = wn * 32 + ns * 8 + t4 * 2;
                    *(float2*)(out + (size_t)grow * FF + col) =
                        make_float2(y[ms][ns][h * 2], y[ms][ns][h * 2 + 1]);
                }
            }
    } else {
        __syncthreads();   // stats phase fully done before partS reuse
#pragma unroll
        for (int ms = 0; ms < 2; ++ms) {
            float p0 = 0.f, p1 = 0.f;
#pragma unroll
            for (int ns = 0; ns < 4; ++ns) {
                p0 += y[ms][ns][0] * lwv[ns].x + y[ms][ns][1] * lwv[ns].y;
                p1 += y[ms][ns][2] * lwv[ns].x + y[ms][ns][3] * lwv[ns].y;
            }
#pragma unroll
            for (int o = 1; o <= 2; o <<= 1) {
                p0 += __shfl_xor_sync(0xffffffffu, p0, o);
                p1 += __shfl_xor_sync(0xffffffffu, p1, o);
            }
            if (t4 == 0) {
                int r0 = wm * 32 + ms * 16 + g;
                partS[wn * 64 + r0] = p0;
                partS[wn * 64 + r0 + 8] = p1;
            }
        }
        __syncthreads();
        if (tid < 64) {
            float s = 0.f;
#pragma unroll
            for (int w = 0; w < 8; ++w) s += partS[w * 64 + tid];
            out[bm + tid] = fmaxf(s + lb[0], 0.f);
        }
    }
}

// ------- length regulation: index-lookup copy, 2 float4/thread, 1 row/warp ---
__global__ void length_reg_kernel(const float* __restrict__ x,
                                  float* __restrict__ out) {
    unsigned tidg = blockIdx.x * 256u + threadIdx.x;  // over 16*4096*32 slots
    int c8 = tidg & 31;                // 32B chunk within row
    int nt = tidg >> 5;                // n*4096 + t (uniform across warp)
    int l = __ldg(g_idx + nt);         // broadcast load
    int n = nt >> 12;
    float4 v0 = make_float4(0.f, 0.f, 0.f, 0.f);
    float4 v1 = v0;
    if (l >= 0) {
        const float4* src = (const float4*)(x + ((n << 9) + l) * DD) + c8 * 2;
        v0 = src[0];
        v1 = src[1];
    }
    float4* dst = (float4*)(out + (size_t)nt * DD) + c8 * 2;
    __stcs(dst, v0);
    __stcs(dst + 1, v1);
}

// ---------------- launch (strictly serial, single stream) ----------------
extern "C" void kernel_launch(void* const* d_in, const int* in_sizes, int n_in,
                              void* d_out, int out_size) {
    const float* x   = (const float*)d_in[0];
    const float* c1w = (const float*)d_in[1];
    const float* c1b = (const float*)d_in[2];
    const float* g1  = (const float*)d_in[3];
    const float* b1  = (const float*)d_in[4];
    const float* c2w = (const float*)d_in[5];
    const float* c2b = (const float*)d_in[6];
    const float* g2  = (const float*)d_in[7];
    const float* b2  = (const float*)d_in[8];
    const float* lw  = (const float*)d_in[9];
    const float* lb  = (const float*)d_in[10];
    const int*   tgt = (const int*)d_in[11];

    float* out = (float*)d_out;                         // [16,4096,256]
    float* dpo = out + (size_t)NB * TT * DD;            // [16,512]

    float* h1;
    __nv_bfloat16 *b1hi, *b1lo, *b2hi, *b2lo;
    cudaGetSymbolAddress((void**)&h1, g_h1);
    cudaGetSymbolAddress((void**)&b1hi, g_b1hi);
    cudaGetSymbolAddress((void**)&b1lo, g_b1lo);
    cudaGetSymbolAddress((void**)&b2hi, g_b2hi);
    cudaGetSymbolAddress((void**)&b2lo, g_b2lo);

    cudaFuncSetAttribute(conv_fused_kernel<false>,
                         cudaFuncAttributeMaxDynamicSharedMemorySize, SMEM_CONV);
    cudaFuncSetAttribute(conv_fused_kernel<true>,
                         cudaFuncAttributeMaxDynamicSharedMemorySize, SMEM_CONV);

    prep_b_cumsum_kernel<<<769, 256>>>(c1w, c2w, tgt);
    conv_fused_kernel<false><<<128, 512, SMEM_CONV>>>(x, b1hi, b1lo, c1b, g1, b1,
                                                      nullptr, nullptr, h1);
    conv_fused_kernel<true><<<128, 512, SMEM_CONV>>>(h1, b2hi, b2lo, c2b, g2, b2,
                                                     lw, lb, dpo);
    length_reg_kernel<<<NB * TT * 32 / 256, 256>>>(x, out);
}

// round 17
// speedup vs baseline: 1.0445x; 1.0445x over previous
#include <cuda_runtime.h>
#include <cuda_bf16.h>
#include <cstdint>
#include <math.h>

// Problem constants
#define NB   16
#define LL   512
#define DD   256
#define FF   256
#define TT   4096
#define MM   (NB * LL)        // 8192 rows
#define KTOT 768              // D * 3
#define EPS  1e-5f

// ---------------- scratch (static device globals; no allocs) ----------------
__device__ __align__(16) float g_h1[MM * FF];
__device__ __align__(16) __nv_bfloat16 g_b1hi[FF * KTOT];
__device__ __align__(16) __nv_bfloat16 g_b1lo[FF * KTOT];
__device__ __align__(16) __nv_bfloat16 g_b2hi[FF * KTOT];
__device__ __align__(16) __nv_bfloat16 g_b2lo[FF * KTOT];
__device__ int   g_idx[NB * TT];    // length-regulation gather index (-1 = pad)

// ==== fused weight prep (blocks 0..767) + cumsum->index scatter (block 768) ==
__global__ void prep_b_cumsum_kernel(const float* __restrict__ w1,
                                     const float* __restrict__ w2,
                                     const int* __restrict__ target) {
    if (blockIdx.x == 768) {
        // 256 threads = 8 warps; warp w handles sequences 2w, 2w+1
        int wid = threadIdx.x >> 5, lane = threadIdx.x & 31;
#pragma unroll
        for (int r = 0; r < 2; ++r) {
            int n = wid * 2 + r;
            const int* src = target + n * LL + lane * 16;
            int v[16];
#pragma unroll
            for (int j = 0; j < 4; ++j)
                *(int4*)(v + j * 4) = *(const int4*)(src + j * 4);
#pragma unroll
            for (int j = 1; j < 16; ++j) v[j] += v[j - 1];
            int total = v[15];
            int pre = total;
#pragma unroll
            for (int o = 1; o < 32; o <<= 1) {
                int t = __shfl_up_sync(0xffffffffu, pre, o);
                if (lane >= o) pre += t;
            }
            pre -= total;   // exclusive prefix before this lane's chunk
#pragma unroll
            for (int j = 0; j < 16; ++j) v[j] += pre;   // global inclusive
            // scatter: element l=lane*16+j covers t in [start, v[j])
            int* idxn = g_idx + n * TT;
            int start = pre;
#pragma unroll
            for (int j = 0; j < 16; ++j) {
                int l = lane * 16 + j;
                for (int t = start; t < v[j]; ++t) idxn[t] = l;
                start = v[j];
            }
            int tot = __shfl_sync(0xffffffffu, v[15], 31);
            for (int t = tot + lane; t < TT; t += 32) idxn[t] = -1;
        }
        return;
    }
    int i = blockIdx.x * 256 + threadIdx.x;     // over 256*768
    int f = i / KTOT;
    int kf = i - f * KTOT;
    int k = kf >> 8;
    int d = kf & 255;
    float v1 = w1[f * KTOT + d * 3 + k];
    float v2 = w2[f * KTOT + d * 3 + k];
    __nv_bfloat16 h1 = __float2bfloat16_rn(v1);
    __nv_bfloat16 h2 = __float2bfloat16_rn(v2);
    g_b1hi[i] = h1;
    g_b1lo[i] = __float2bfloat16_rn(v1 - __bfloat162float(h1));
    g_b2hi[i] = h2;
    g_b2lo[i] = __float2bfloat16_rn(v2 - __bfloat162float(h2));
}

// ============== fused conv(K=3) GEMM + LayerNorm + ReLU (+ linear) ==========
// Per CTA: 64 rows x 256 cols. 512 threads = 16 warps (2m x 8n), warp tile 32x32.
// K loop: 24 chunks of 32 (3 taps x 8 d-chunks), bf16 hi/lo 3-pass HMMA.
// (R6-proven scalar-LDS fragment path; ldmatrix variant measured slower.)

#define ST_BYTES   51200            // one stage: Ahi|Alo|Bhi|Blo (80B rows)
#define OFF_AHI    0                // 64 rows x 80B
#define OFF_ALO    5120
#define OFF_BHI    10240            // 256 rows x 80B
#define OFF_BLO    30720
#define OFF_PART_S (2 * ST_BYTES)           // 8 x 64 floats
#define OFF_PART_Q (OFF_PART_S + 2048)
#define OFF_MEAN   (OFF_PART_Q + 2048)      // 64 floats
#define OFF_RSTD   (OFF_MEAN + 256)
#define SMEM_CONV  (OFF_RSTD + 256)

__device__ __forceinline__ void hmma(float* d, const uint32_t* a, const uint32_t* b) {
    asm volatile(
        "mma.sync.aligned.m16n8k16.row.col.f32.bf16.bf16.f32 "
        "{%0,%1,%2,%3}, {%4,%5,%6,%7}, {%8,%9}, {%0,%1,%2,%3};"
        : "+f"(d[0]), "+f"(d[1]), "+f"(d[2]), "+f"(d[3])
        : "r"(a[0]), "r"(a[1]), "r"(a[2]), "r"(a[3]), "r"(b[0]), "r"(b[1]));
}

__device__ __forceinline__ uint32_t pack2(float a, float b) {
    __nv_bfloat162 t = __floats2bfloat162_rn(a, b);
    return *reinterpret_cast<uint32_t*>(&t);
}

template <bool DO_LIN>
__global__ __launch_bounds__(512, 1)
void conv_fused_kernel(const float* __restrict__ A,
                       const __nv_bfloat16* __restrict__ Bhi,
                       const __nv_bfloat16* __restrict__ Blo,
                       const float* __restrict__ bias,
                       const float* __restrict__ gam,
                       const float* __restrict__ bet,
                       const float* __restrict__ lw,
                       const float* __restrict__ lb,
                       float* __restrict__ out)   // h1 if !DO_LIN, dpo if DO_LIN
{
    extern __shared__ char smem[];
    const int tid = threadIdx.x;
    const int wid = tid >> 5;
    const int lane = tid & 31;
    const int g = lane >> 2;          // groupID
    const int t4 = lane & 3;          // thread-in-group
    const int wm = wid >> 3;          // 0..1
    const int wn = wid & 7;           // 0..7
    const int bm = blockIdx.x * 64;
    const int n = bm >> 9;
    const int l0 = bm & 511;

    float4 aval;
    uint4  bhv[2], blv[2];
    const int arow = tid >> 3;        // A: row 0..63
    const int akq = tid & 7;          // float4 along d
    const int brow0 = tid >> 2, bkq0 = tid & 3;
    const int brow1 = (tid + 512) >> 2, bkq1 = tid & 3;

    auto prefetch = [&](int c) {
        const int tap = c >> 3;
        const int dc = (c & 7) * 32;
        int lsrc = l0 + arow + tap - 1;
        aval = make_float4(0.f, 0.f, 0.f, 0.f);
        if (lsrc >= 0 && lsrc < LL)
            aval = *(const float4*)(A + (size_t)((n << 9) + lsrc) * DD + dc + akq * 4);
        const int kfb = tap * 256 + dc;
        bhv[0] = *(const uint4*)(Bhi + (size_t)brow0 * KTOT + kfb + bkq0 * 8);
        bhv[1] = *(const uint4*)(Bhi + (size_t)brow1 * KTOT + kfb + bkq1 * 8);
        blv[0] = *(const uint4*)(Blo + (size_t)brow0 * KTOT + kfb + bkq0 * 8);
        blv[1] = *(const uint4*)(Blo + (size_t)brow1 * KTOT + kfb + bkq1 * 8);
    };

    auto store_stage = [&](int s) {
        char* stg = smem + s * ST_BYTES;
        __nv_bfloat16 hx = __float2bfloat16_rn(aval.x);
        __nv_bfloat16 hy = __float2bfloat16_rn(aval.y);
        __nv_bfloat16 hz = __float2bfloat16_rn(aval.z);
        __nv_bfloat16 hw = __float2bfloat16_rn(aval.w);
        uint32_t hi01, hi23;
        { __nv_bfloat162 p; p.x = hx; p.y = hy; hi01 = *reinterpret_cast<uint32_t*>(&p); }
        { __nv_bfloat162 p; p.x = hz; p.y = hw; hi23 = *reinterpret_cast<uint32_t*>(&p); }
        uint32_t lo01 = pack2(aval.x - __bfloat162float(hx), aval.y - __bfloat162float(hy));
        uint32_t lo23 = pack2(aval.z - __bfloat162float(hz), aval.w - __bfloat162float(hw));
        *(uint2*)(stg + OFF_AHI + arow * 80 + akq * 8) = make_uint2(hi01, hi23);
        *(uint2*)(stg + OFF_ALO + arow * 80 + akq * 8) = make_uint2(lo01, lo23);
        *(uint4*)(stg + OFF_BHI + brow0 * 80 + bkq0 * 16) = bhv[0];
        *(uint4*)(stg + OFF_BHI + brow1 * 80 + bkq1 * 16) = bhv[1];
        *(uint4*)(stg + OFF_BLO + brow0 * 80 + bkq0 * 16) = blv[0];
        *(uint4*)(stg + OFF_BLO + brow1 * 80 + bkq1 * 16) = blv[1];
    };

    float acc[2][4][4];
#pragma unroll
    for (int i = 0; i < 2; i++)
#pragma unroll
        for (int j = 0; j < 4; j++)
#pragma unroll
            for (int c = 0; c < 4; c++) acc[i][j][c] = 0.f;

    // prologue: stage 0 stored, regs hold chunk 1
    prefetch(0);
    store_stage(0);
    prefetch(1);

#pragma unroll 1
    for (int c = 0; c < 24; ++c) {
        __syncthreads();   // buf c&1 published; buf (c+1)&1 free for overwrite
        if (c < 23) store_stage((c + 1) & 1);   // from regs prefetched at c-1
        if (c < 22) prefetch(c + 2);            // LDGs overlap compute(c)
        const char* stg = smem + (c & 1) * ST_BYTES;
#pragma unroll
        for (int ks = 0; ks < 2; ++ks) {
            uint32_t ah[2][4], al[2][4], bh[4][2], bl[4][2];
#pragma unroll
            for (int ms = 0; ms < 2; ++ms) {
                const char* base = stg + OFF_AHI + (wm * 32 + ms * 16 + g) * 80 + ks * 32 + t4 * 4;
                ah[ms][0] = *(const uint32_t*)(base);
                ah[ms][1] = *(const uint32_t*)(base + 8 * 80);
                ah[ms][2] = *(const uint32_t*)(base + 16);
                ah[ms][3] = *(const uint32_t*)(base + 8 * 80 + 16);
            }
#pragma unroll
            for (int ns = 0; ns < 4; ++ns) {
                const char* base = stg + OFF_BHI + (wn * 32 + ns * 8 + g) * 80 + ks * 32 + t4 * 4;
                bh[ns][0] = *(const uint32_t*)(base);
                bh[ns][1] = *(const uint32_t*)(base + 16);
            }
#pragma unroll
            for (int ms = 0; ms < 2; ++ms)
#pragma unroll
                for (int ns = 0; ns < 4; ++ns) hmma(acc[ms][ns], ah[ms], bh[ns]);
#pragma unroll
            for (int ns = 0; ns < 4; ++ns) {
                const char* base = stg + OFF_BLO + (wn * 32 + ns * 8 + g) * 80 + ks * 32 + t4 * 4;
                bl[ns][0] = *(const uint32_t*)(base);
                bl[ns][1] = *(const uint32_t*)(base + 16);
            }
#pragma unroll
            for (int ms = 0; ms < 2; ++ms)
#pragma unroll
                for (int ns = 0; ns < 4; ++ns) hmma(acc[ms][ns], ah[ms], bl[ns]);
#pragma unroll
            for (int ms = 0; ms < 2; ++ms) {
                const char* base = stg + OFF_ALO + (wm * 32 + ms * 16 + g) * 80 + ks * 32 + t4 * 4;
                al[ms][0] = *(const uint32_t*)(base);
                al[ms][1] = *(const uint32_t*)(base + 8 * 80);
                al[ms][2] = *(const uint32_t*)(base + 16);
                al[ms][3] = *(const uint32_t*)(base + 8 * 80 + 16);
            }
#pragma unroll
            for (int ms = 0; ms < 2; ++ms)
#pragma unroll
                for (int ns = 0; ns < 4; ++ns) hmma(acc[ms][ns], al[ms], bh[ns]);
        }
    }

    // ---------------- epilogue: bias + LayerNorm + ReLU (+ linear) ----------------
    float* partS = (float*)(smem + OFF_PART_S);   // [8][64]
    float* partQ = (float*)(smem + OFF_PART_Q);   // [8][64]
    float* meanA = (float*)(smem + OFF_MEAN);     // [64]
    float* rstdA = (float*)(smem + OFF_RSTD);     // [64]

    float2 bs[4], gm[4], bt[4], lwv[4];
#pragma unroll
    for (int ns = 0; ns < 4; ++ns) {
        int col = wn * 32 + ns * 8 + t4 * 2;
        bs[ns] = *(const float2*)(bias + col);
        gm[ns] = *(const float2*)(gam + col);
        bt[ns] = *(const float2*)(bet + col);
        if (DO_LIN) lwv[ns] = *(const float2*)(lw + col);
    }
#pragma unroll
    for (int ms = 0; ms < 2; ++ms)
#pragma unroll
        for (int ns = 0; ns < 4; ++ns) {
            acc[ms][ns][0] += bs[ns].x; acc[ms][ns][1] += bs[ns].y;
            acc[ms][ns][2] += bs[ns].x; acc[ms][ns][3] += bs[ns].y;
        }
    __syncthreads();   // mainloop smem reads done before stats-area writes
#pragma unroll
    for (int ms = 0; ms < 2; ++ms) {
        float s0 = 0.f, q0 = 0.f, s1 = 0.f, q1 = 0.f;
#pragma unroll
        for (int ns = 0; ns < 4; ++ns) {
            s0 += acc[ms][ns][0] + acc[ms][ns][1];
            q0 += acc[ms][ns][0] * acc[ms][ns][0] + acc[ms][ns][1] * acc[ms][ns][1];
            s1 += acc[ms][ns][2] + acc[ms][ns][3];
            q1 += acc[ms][ns][2] * acc[ms][ns][2] + acc[ms][ns][3] * acc[ms][ns][3];
        }
#pragma unroll
        for (int o = 1; o <= 2; o <<= 1) {
            s0 += __shfl_xor_sync(0xffffffffu, s0, o);
            q0 += __shfl_xor_sync(0xffffffffu, q0, o);
            s1 += __shfl_xor_sync(0xffffffffu, s1, o);
            q1 += __shfl_xor_sync(0xffffffffu, q1, o);
        }
        if (t4 == 0) {
            int r0 = wm * 32 + ms * 16 + g;
            partS[wn * 64 + r0] = s0;      partQ[wn * 64 + r0] = q0;
            partS[wn * 64 + r0 + 8] = s1;  partQ[wn * 64 + r0 + 8] = q1;
        }
    }
    __syncthreads();
    if (tid < 64) {
        float s = 0.f, q = 0.f;
#pragma unroll
        for (int w = 0; w < 8; ++w) { s += partS[w * 64 + tid]; q += partQ[w * 64 + tid]; }
        float mean = s * (1.f / 256.f);
        float var = q * (1.f / 256.f) - mean * mean;
        meanA[tid] = mean;
        rstdA[tid] = rsqrtf(var + EPS);
    }
    __syncthreads();

    float mu[2][2], rs[2][2];
#pragma unroll
    for (int ms = 0; ms < 2; ++ms)
#pragma unroll
        for (int h = 0; h < 2; ++h) {
            int lr = wm * 32 + ms * 16 + h * 8 + g;
            mu[ms][h] = meanA[lr];
            rs[ms][h] = rstdA[lr];
        }
    float y[2][4][4];
#pragma unroll
    for (int ms = 0; ms < 2; ++ms)
#pragma unroll
        for (int ns = 0; ns < 4; ++ns) {
            y[ms][ns][0] = fmaxf((acc[ms][ns][0] - mu[ms][0]) * rs[ms][0] * gm[ns].x + bt[ns].x, 0.f);
            y[ms][ns][1] = fmaxf((acc[ms][ns][1] - mu[ms][0]) * rs[ms][0] * gm[ns].y + bt[ns].y, 0.f);
            y[ms][ns][2] = fmaxf((acc[ms][ns][2] - mu[ms][1]) * rs[ms][1] * gm[ns].x + bt[ns].x, 0.f);
            y[ms][ns][3] = fmaxf((acc[ms][ns][3] - mu[ms][1]) * rs[ms][1] * gm[ns].y + bt[ns].y, 0.f);
        }

    if (!DO_LIN) {
#pragma unroll
        for (int ms = 0; ms < 2; ++ms)
#pragma unroll
            for (int h = 0; h < 2; ++h) {
                int grow = bm + wm * 32 + ms * 16 + h * 8 + g;
#pragma unroll
                for (int ns = 0; ns < 4; ++ns) {
                    int col = wn * 32 + ns * 8 + t4 * 2;
                    *(float2*)(out + (size_t)grow * FF + col) =
                        make_float2(y[ms][ns][h * 2], y[ms][ns][h * 2 + 1]);
                }
            }
    } else {
        __syncthreads();   // stats phase fully done before partS reuse
#pragma unroll
        for (int ms = 0; ms < 2; ++ms) {
            float p0 = 0.f, p1 = 0.f;
#pragma unroll
            for (int ns = 0; ns < 4; ++ns) {
                p0 += y[ms][ns][0] * lwv[ns].x + y[ms][ns][1] * lwv[ns].y;
                p1 += y[ms][ns][2] * lwv[ns].x + y[ms][ns][3] * lwv[ns].y;
            }
#pragma unroll
            for (int o = 1; o <= 2; o <<= 1) {
                p0 += __shfl_xor_sync(0xffffffffu, p0, o);
                p1 += __shfl_xor_sync(0xffffffffu, p1, o);
            }
            if (t4 == 0) {
                int r0 = wm * 32 + ms * 16 + g;
                partS[wn * 64 + r0] = p0;
                partS[wn * 64 + r0 + 8] = p1;
            }
        }
        __syncthreads();
        if (tid < 64) {
            float s = 0.f;
#pragma unroll
            for (int w = 0; w < 8; ++w) s += partS[w * 64 + tid];
            out[bm + tid] = fmaxf(s + lb[0], 0.f);
        }
    }
}

// ------- length regulation: index-lookup copy (R7-measured-best variant) -----
__global__ void length_reg_kernel(const float* __restrict__ x,
                                  float* __restrict__ out) {
    unsigned tidg = blockIdx.x * 256u + threadIdx.x;  // over 16*4096*64 float4
    int c4 = tidg & 63;
    int nt = tidg >> 6;                // n*4096 + t
    int l = __ldg(g_idx + nt);
    int n = nt >> 12;
    float4 v = make_float4(0.f, 0.f, 0.f, 0.f);
    if (l >= 0)
        v = *(const float4*)(x + ((n << 9) + l) * DD + c4 * 4);
    __stcs((float4*)(out + (size_t)tidg * 4), v);
}

// ---------------- launch (strictly serial, single stream) ----------------
extern "C" void kernel_launch(void* const* d_in, const int* in_sizes, int n_in,
                              void* d_out, int out_size) {
    const float* x   = (const float*)d_in[0];
    const float* c1w = (const float*)d_in[1];
    const float* c1b = (const float*)d_in[2];
    const float* g1  = (const float*)d_in[3];
    const float* b1  = (const float*)d_in[4];
    const float* c2w = (const float*)d_in[5];
    const float* c2b = (const float*)d_in[6];
    const float* g2  = (const float*)d_in[7];
    const float* b2  = (const float*)d_in[8];
    const float* lw  = (const float*)d_in[9];
    const float* lb  = (const float*)d_in[10];
    const int*   tgt = (const int*)d_in[11];

    float* out = (float*)d_out;                         // [16,4096,256]
    float* dpo = out + (size_t)NB * TT * DD;            // [16,512]

    float* h1;
    __nv_bfloat16 *b1hi, *b1lo, *b2hi, *b2lo;
    cudaGetSymbolAddress((void**)&h1, g_h1);
    cudaGetSymbolAddress((void**)&b1hi, g_b1hi);
    cudaGetSymbolAddress((void**)&b1lo, g_b1lo);
    cudaGetSymbolAddress((void**)&b2hi, g_b2hi);
    cudaGetSymbolAddress((void**)&b2lo, g_b2lo);

    cudaFuncSetAttribute(conv_fused_kernel<false>,
                         cudaFuncAttributeMaxDynamicSharedMemorySize, SMEM_CONV);
    cudaFuncSetAttribute(conv_fused_kernel<true>,
                         cudaFuncAttributeMaxDynamicSharedMemorySize, SMEM_CONV);

    prep_b_cumsum_kernel<<<769, 256>>>(c1w, c2w, tgt);
    conv_fused_kernel<false><<<128, 512, SMEM_CONV>>>(x, b1hi, b1lo, c1b, g1, b1,
                                                      nullptr, nullptr, h1);
    conv_fused_kernel<true><<<128, 512, SMEM_CONV>>>(h1, b2hi, b2lo, c2b, g2, b2,
                                                     lw, lb, dpo);
    length_reg_kernel<<<(NB * TT * (DD / 4)) / 256, 256>>>(x, out);
}